// round 16
// baseline (speedup 1.0000x reference)
#include <cuda_runtime.h>
#include <math.h>

#define BD 8
#define NN 2048
#define DD 768
#define HH 12
#define GBB 1025
#define LBB 9
#define NWW 255
#define HOPP 8
#define NCG (HH * GBB)  // 12300
#define NCL (HH * LBB)  // 108
#define NCG2 (NCG / 2)  // 6150 float2 columns
#define NCL2 (NCL / 2)  // 54
#define KS2 24          // mlp2 split-K chunks
#define PADI(n) ((n) + ((n) >> 4))

// ---------------- scratch ----------------
__device__ float g_xT[BD * DD * NN];        // (B, D, N): x^T, then y = x + fused
__device__ float g_ctxp[BD * 64 * DD];
__device__ float2 g_p1[2 * 24 * BD * (DD / 2)];
__device__ float g_hg[BD * DD];
__device__ float g_hl[BD * DD];
__device__ float2 g_pg[KS2 * BD * NCG2];
__device__ float2 g_pl[KS2 * BD * NCL2];
__device__ float g_mg[BD * NCG];
__device__ float g_ml[BD * NCL];
__device__ float2 g_tw[1025];               // exp(-i*pi*k/1024)

__device__ __forceinline__ float2 cmul(float2 a, float2 b) {
    return make_float2(a.x * b.x - a.y * b.y, a.x * b.y + a.y * b.x);
}
__device__ __forceinline__ float2 cadd(float2 a, float2 b) {
    return make_float2(a.x + b.x, a.y + b.y);
}
__device__ __forceinline__ float2 csub(float2 a, float2 b) {
    return make_float2(a.x - b.x, a.y - b.y);
}

// modrelu rescale: max(a+bias,0)/max(a,1e-6) with a=sqrt(m)
__device__ __forceinline__ float mr_scale(float m, float bias) {
    if (m >= 1e-12f) return fmaxf(fmaf(bias, rsqrtf(m), 1.0f), 0.0f);
    return fmaxf(sqrtf(m) + bias, 0.0f) * 1e6f;
}

__device__ __forceinline__ float2 filt_modrelu(float2 v, float pg, float bias) {
    v.x *= pg;
    v.y *= pg;
    float sc = mr_scale(v.x * v.x + v.y * v.y, bias);
    v.x *= sc;
    v.y *= sc;
    return v;
}

// ---------------- transpose in + ctx partials + twiddle init ----------------
__global__ __launch_bounds__(256) void tr_in_kernel(const float* __restrict__ x) {
    __shared__ float tile[32][33];
    __shared__ float red[8][32];
    int b = blockIdx.z;
    int d0 = blockIdx.x * 32;
    int n0 = blockIdx.y * 32;
    int tx = threadIdx.x, ty = threadIdx.y;
    int tid = ty * 32 + tx;

    if (blockIdx.y == 0 && blockIdx.z == 0) {
        int k = blockIdx.x * 256 + tid;
        if (k <= 1024) {
            float ang = -(float)M_PI * (float)k * (1.0f / 1024.0f);
            float sv, cv;
            sincosf(ang, &sv, &cv);
            g_tw[k] = make_float2(cv, sv);
        }
    }

    const float* xp = x + ((size_t)(b * NN + n0 + ty)) * DD + d0 + tx;
    float p = 0.f;
#pragma unroll
    for (int i = 0; i < 4; i++) {
        float v = xp[(size_t)i * 8 * DD];
        tile[ty + 8 * i][tx] = v;
        p += v;
    }
    red[ty][tx] = p;
    __syncthreads();
    if (ty == 0) {
        float s = 0.f;
#pragma unroll
        for (int j = 0; j < 8; j++) s += red[j][tx];
        g_ctxp[(size_t)(b * 64 + blockIdx.y) * DD + d0 + tx] = s;
    }
    float* op = g_xT + ((size_t)(b * DD + d0 + ty)) * NN + n0 + tx;
#pragma unroll
    for (int i = 0; i < 4; i++) op[(size_t)i * 8 * NN] = tile[tx][ty + 8 * i];
}

// ---------------- mlp layer 1 (split-K partials, float2 cols, ctx reduce folded) --
__global__ __launch_bounds__(128) void mlp1_part_kernel(const float* __restrict__ w1g,
                                                        const float* __restrict__ w1l) {
    int cb = blockIdx.x % 3;
    int ks = blockIdx.x / 3;   // 0..23
    int b = blockIdx.y;
    int z = blockIdx.z;
    const float2* w = (const float2*)(z ? w1l : w1g);
    __shared__ float csp[128];
    __shared__ float cs[32];
    int k0 = ks * 32;
    {
        int kk = threadIdx.x & 31;
        int sl = threadIdx.x >> 5;
        const float* pp = g_ctxp + (size_t)b * 64 * DD + k0 + kk + (size_t)sl * 16 * DD;
        float s = 0.f;
#pragma unroll
        for (int j = 0; j < 16; j++) s += pp[(size_t)j * DD];
        csp[threadIdx.x] = s;
    }
    __syncthreads();
    if (threadIdx.x < 32) {
        float s = csp[threadIdx.x] + csp[threadIdx.x + 32] + csp[threadIdx.x + 64] +
                  csp[threadIdx.x + 96];
        cs[threadIdx.x] = s * (1.0f / (float)NN);
    }
    __syncthreads();
    int c2 = cb * 128 + threadIdx.x;
    const float2* wp = w + (size_t)k0 * (DD / 2) + c2;
    float2 acc = make_float2(0.f, 0.f);
#pragma unroll
    for (int kk = 0; kk < 32; kk++) {
        float2 wv = wp[(size_t)kk * (DD / 2)];
        float cv = cs[kk];
        acc.x += cv * wv.x;
        acc.y += cv * wv.y;
    }
    g_p1[((z * 24 + ks) * BD + b) * (DD / 2) + c2] = acc;
}

// ---------------- mlp layer 1 finish: GELU (float2) ----------------
__global__ __launch_bounds__(128) void mlp1_fin_kernel(const float* __restrict__ b1g,
                                                       const float* __restrict__ b1l) {
    int c2 = blockIdx.x * 128 + threadIdx.x;
    int b = blockIdx.y;
    int z = blockIdx.z;
    const float2* bias = (const float2*)(z ? b1l : b1g);
    float2* out = (float2*)(z ? g_hl : g_hg);
    float2 s = bias[c2];
#pragma unroll
    for (int ks = 0; ks < 24; ks++) {
        float2 v = g_p1[((z * 24 + ks) * BD + b) * (DD / 2) + c2];
        s.x += v.x;
        s.y += v.y;
    }
    out[b * (DD / 2) + c2] =
        make_float2(0.5f * s.x * (1.0f + erff(s.x * 0.70710678118654752f)),
                    0.5f * s.y * (1.0f + erff(s.y * 0.70710678118654752f)));
}

// ---------------- mlp layer 2 (deep split-K, float2 columns) ----------------
__global__ __launch_bounds__(128) void mlp2_part_kernel(const float* __restrict__ w2g,
                                                        const float* __restrict__ w2l) {
    bool isl = (blockIdx.x == 49);
    int by = blockIdx.y;      // k-chunk 0..23
    int k0 = by * 32;
    __shared__ float hs[BD * 32];
    const float* h = isl ? g_hl : g_hg;
    if (threadIdx.x < BD * 32 / 2) {
        int i = threadIdx.x * 2;
        int b = i >> 5, kk = i & 31;
        hs[i] = h[b * DD + k0 + kk];
        hs[i + 1] = h[b * DD + k0 + kk + 1];
    }
    __syncthreads();
    int ncol2 = isl ? NCL2 : NCG2;
    int c2 = isl ? threadIdx.x : blockIdx.x * 128 + threadIdx.x;
    if (c2 >= ncol2) return;
    const float2* w = (const float2*)(isl ? w2l : w2g);
    float2* pp = isl ? g_pl : g_pg;
    float2 acc[BD];
#pragma unroll
    for (int b = 0; b < BD; b++) acc[b] = make_float2(0.f, 0.f);
    const float2* wp = w + (size_t)k0 * ncol2 + c2;
#pragma unroll
    for (int kk = 0; kk < 32; kk++) {
        float2 wv = wp[(size_t)kk * ncol2];
#pragma unroll
        for (int b = 0; b < BD; b++) {
            float hv = hs[b * 32 + kk];
            acc[b].x += hv * wv.x;
            acc[b].y += hv * wv.y;
        }
    }
#pragma unroll
    for (int b = 0; b < BD; b++) pp[(size_t)(by * BD + b) * ncol2 + c2] = acc[b];
}

__global__ __launch_bounds__(128) void mlp2_fin_kernel(const float* __restrict__ b2g,
                                                       const float* __restrict__ b2l) {
    bool isl = (blockIdx.x == 49);
    int ncol2 = isl ? NCL2 : NCG2;
    int c2 = isl ? threadIdx.x : blockIdx.x * 128 + threadIdx.x;
    if (c2 >= ncol2) return;
    int b = blockIdx.y;
    const float2* bias = (const float2*)(isl ? b2l : b2g);
    const float2* pp = isl ? g_pl : g_pg;
    float2* out = (float2*)(isl ? g_ml : g_mg);
    float2 s = bias[c2];
#pragma unroll
    for (int ks = 0; ks < KS2; ks++) {
        float2 v = pp[(size_t)(ks * BD + b) * ncol2 + c2];
        s.x += v.x;
        s.y += v.y;
    }
    out[(size_t)b * ncol2 + c2] = make_float2(tanhf(s.x), tanhf(s.y));
}

// ---------------- generic radix-4 Stockham stage (twiddle via __ldg, w2=w1^2) -----
template <bool INV>
__device__ __forceinline__ void fstage(const float2* __restrict__ src,
                                       float2* __restrict__ dst, int t, int tid) {
    const int s = 1 << (2 * t);
    int q = tid & (s - 1);
    int ps = tid - q;
    float2 a = src[tid];
    float2 b = src[tid + 256];
    float2 c = src[tid + 512];
    float2 d = src[tid + 768];
    float2 w1 = __ldg(&g_tw[2 * ps]);
    if (INV) w1.y = -w1.y;
    float2 w2 = cmul(w1, w1);
    float2 w3 = cmul(w1, w2);
    float2 apc = cadd(a, c);
    float2 amc = csub(a, c);
    float2 bpd = cadd(b, d);
    float2 bmd = csub(b, d);
    int o = 4 * tid - 3 * q;
    dst[o] = cadd(apc, bpd);
    float2 t1, t3;
    if (!INV) {
        t1 = make_float2(amc.x + bmd.y, amc.y - bmd.x);
        t3 = make_float2(amc.x - bmd.y, amc.y + bmd.x);
    } else {
        t1 = make_float2(amc.x - bmd.y, amc.y + bmd.x);
        t3 = make_float2(amc.x + bmd.y, amc.y - bmd.x);
    }
    dst[o + s] = cmul(t1, w1);
    dst[o + 2 * s] = cmul(csub(apc, bpd), w2);
    dst[o + 3 * s] = cmul(t3, w3);
}

__global__ __launch_bounds__(256, 4) void spectral_kernel(
    const float* __restrict__ base_g, const float* __restrict__ base_l,
    const float* __restrict__ bias_g, const float* __restrict__ bias_l,
    const float* __restrict__ fusion_w) {
    __shared__ float2 uA[1088];        // union: padded s_time (2176 floats) / bufA
    __shared__ float2 bufB[1024];
    __shared__ float s_xl[2176];       // padded overlap-add output (write-once)
    __shared__ float2 glb[9];          // {0.25*(base+ml), bias} per local freq
    __shared__ float2 stg[8][8];       // warp-boundary staging for OA shuffle
    float2* __restrict__ bufA = uA;
    float* __restrict__ s_time = (float*)uA;

    const int tid = threadIdx.x;
    const int blk = blockIdx.x;
    const int b = blk / DD;
    const int c = blk - b * DD;
    const int h = c >> 6;
    const float invs = 0.022097086912079608f;  // 1/sqrt(2048)
    const float r2 = 0.70710678118654752f;

    if (tid < 9)
        glb[tid] = make_float2(0.25f * (base_l[h * LBB + tid] + g_ml[(b * HH + h) * LBB + tid]),
                               bias_l[h * LBB + tid]);

    float* row = g_xT + (size_t)blk * NN;
    {
        const float4* src4 = (const float4*)row;
        for (int i = tid; i < 512; i += 256) {
            float4 v = src4[i];
            int p = PADI(4 * i);
            s_time[p] = v.x;
            s_time[p + 1] = v.y;
            s_time[p + 2] = v.z;
            s_time[p + 3] = v.w;
        }
    }
    __syncthreads();

    // -------- local STFT: single pass; shuffle-based write-once overlap-add ------
    {
        const float hq[16] = {0.f, 0.25f * 0.03806023374435663f, 0.25f * 0.14644660940672624f,
                              0.25f * 0.30865828381745508f, 0.25f * 0.5f, 0.25f * 0.69134171618254492f,
                              0.25f * 0.85355339059327376f, 0.25f * 0.96193976625564337f, 0.25f * 1.f,
                              0.25f * 0.96193976625564337f, 0.25f * 0.85355339059327376f,
                              0.25f * 0.69134171618254492f, 0.25f * 0.5f, 0.25f * 0.30865828381745508f,
                              0.25f * 0.14644660940672624f, 0.25f * 0.03806023374435663f};
        const float hw[16] = {0.f, 0.03806023374435663f, 0.14644660940672624f, 0.30865828381745508f,
                              0.5f, 0.69134171618254492f, 0.85355339059327376f, 0.96193976625564337f,
                              1.f, 0.96193976625564337f, 0.85355339059327376f, 0.69134171618254492f,
                              0.5f, 0.30865828381745508f, 0.14644660940672624f, 0.03806023374435663f};
        const float cw[9] = {1.f, 0.92387953251128674f, r2, 0.38268343236508977f, 0.f,
                             -0.38268343236508977f, -r2, -0.92387953251128674f, -1.f};
        const float sw[9] = {0.f, 0.38268343236508977f, r2, 0.92387953251128674f, 1.f,
                             0.92387953251128674f, r2, 0.38268343236508977f, 0.f};

        float2 g[8];
#pragma unroll
        for (int m = 0; m < 8; m++) g[m] = make_float2(0.f, 0.f);
        const int nw = tid;
        const int base = nw * HOPP;
        if (nw < NWW) {
            float tw[16];
            tw[0] = 0.f;
#pragma unroll
            for (int j = 1; j < 16; j++) tw[j] = s_time[PADI(base + j)] * hw[j];

            float2 z[8];
#pragma unroll
            for (int m = 0; m < 8; m++) z[m] = make_float2(tw[2 * m], tw[2 * m + 1]);

            // forward FFT8 (DIF), output bit-reversed
            float2 Z[8];
            {
                float2 a0 = cadd(z[0], z[4]), d0 = csub(z[0], z[4]);
                float2 a1 = cadd(z[1], z[5]), d1 = csub(z[1], z[5]);
                float2 a2 = cadd(z[2], z[6]), d2 = csub(z[2], z[6]);
                float2 a3 = cadd(z[3], z[7]), d3 = csub(z[3], z[7]);
                float2 a4 = d0;
                float2 a5 = make_float2(r2 * (d1.x + d1.y), r2 * (d1.y - d1.x));
                float2 a6 = make_float2(d2.y, -d2.x);
                float2 a7 = make_float2(r2 * (d3.y - d3.x), -r2 * (d3.x + d3.y));

                float2 b0 = cadd(a0, a2), b2 = csub(a0, a2);
                float2 b1 = cadd(a1, a3), t13 = csub(a1, a3);
                float2 b3 = make_float2(t13.y, -t13.x);
                float2 b4 = cadd(a4, a6), b6 = csub(a4, a6);
                float2 b5 = cadd(a5, a7), t57 = csub(a5, a7);
                float2 b7 = make_float2(t57.y, -t57.x);

                Z[0] = cadd(b0, b1);
                Z[4] = csub(b0, b1);
                Z[2] = cadd(b2, b3);
                Z[6] = csub(b2, b3);
                Z[1] = cadd(b4, b5);
                Z[5] = csub(b4, b5);
                Z[3] = cadd(b6, b7);
                Z[7] = csub(b6, b7);
            }

            // unpack to rfft16 + filter + modrelu
            float2 X[9];
#pragma unroll
            for (int k = 0; k <= 4; k++) {
                float2 Zk = Z[k];
                float2 Zm = Z[(8 - k) & 7];
                float2 E = make_float2(0.5f * (Zk.x + Zm.x), 0.5f * (Zk.y - Zm.y));
                float2 O = make_float2(0.5f * (Zk.y + Zm.y), -0.5f * (Zk.x - Zm.x));
                float2 w = make_float2(cw[k], -sw[k]);
                float2 Xk = cadd(E, cmul(w, O));
                float2 gb = glb[k];
                X[k] = filt_modrelu(Xk, gb.x, gb.y);
                if (k > 0 && k < 4) {
                    int kk = 8 - k;
                    float2 wm = make_float2(cw[kk], -sw[kk]);
                    float2 Xm = cadd(make_float2(E.x, -E.y), cmul(wm, make_float2(O.x, -O.y)));
                    float2 gb2 = glb[kk];
                    X[kk] = filt_modrelu(Xm, gb2.x, gb2.y);
                } else if (k == 0) {
                    float2 Xm = make_float2(E.x - O.x, O.y - E.y);
                    float2 gb2 = glb[8];
                    X[8] = filt_modrelu(Xm, gb2.x, gb2.y);
                }
            }

            // repack: G[m] = S + i*conj(w16^m)*D
            float2 G[8];
#pragma unroll
            for (int m = 0; m < 8; m++) {
                float2 Xa = X[m];
                float2 Xb = X[8 - m];
                float2 S = make_float2(Xa.x + Xb.x, Xa.y - Xb.y);
                float2 D = make_float2(Xa.x - Xb.x, Xa.y + Xb.y);
                float2 wc = make_float2(cw[m], sw[m]);
                float2 t = cmul(wc, D);
                G[m] = make_float2(S.x - t.y, S.y + t.x);
            }

            // inverse FFT8 (conjugate twiddles), output bit-reversed
            {
                float2 a0 = cadd(G[0], G[4]), d0 = csub(G[0], G[4]);
                float2 a1 = cadd(G[1], G[5]), d1 = csub(G[1], G[5]);
                float2 a2 = cadd(G[2], G[6]), d2 = csub(G[2], G[6]);
                float2 a3 = cadd(G[3], G[7]), d3 = csub(G[3], G[7]);
                float2 a4 = d0;
                float2 a5 = make_float2(r2 * (d1.x - d1.y), r2 * (d1.x + d1.y));
                float2 a6 = make_float2(-d2.y, d2.x);
                float2 a7 = make_float2(-r2 * (d3.x + d3.y), r2 * (d3.x - d3.y));

                float2 b0 = cadd(a0, a2), b2 = csub(a0, a2);
                float2 b1 = cadd(a1, a3), t13 = csub(a1, a3);
                float2 b3 = make_float2(-t13.y, t13.x);
                float2 b4 = cadd(a4, a6), b6 = csub(a4, a6);
                float2 b5 = cadd(a5, a7), t57 = csub(a5, a7);
                float2 b7 = make_float2(-t57.y, t57.x);

                g[0] = cadd(b0, b1);
                g[4] = csub(b0, b1);
                g[2] = cadd(b2, b3);
                g[6] = csub(b2, b3);
                g[1] = cadd(b4, b5);
                g[5] = csub(b4, b5);
                g[3] = cadd(b6, b7);
                g[7] = csub(b6, b7);
            }
        }

        // fetch previous window's iFFT via shuffle (warp boundary via SMEM stage)
        float2 gp[8];
#pragma unroll
        for (int m = 0; m < 8; m++) {
            gp[m].x = __shfl_up_sync(0xffffffffu, g[m].x, 1);
            gp[m].y = __shfl_up_sync(0xffffffffu, g[m].y, 1);
        }
        int lane = tid & 31;
        if (lane == 31) {
#pragma unroll
            for (int m = 0; m < 8; m++) stg[tid >> 5][m] = g[m];
        }
        __syncthreads();
        if (lane == 0) {
            if (tid == 0) {
#pragma unroll
                for (int m = 0; m < 8; m++) gp[m] = make_float2(0.f, 0.f);
            } else {
#pragma unroll
                for (int m = 0; m < 8; m++) gp[m] = stg[(tid >> 5) - 1][m];
            }
        }
        // thread tid owns outputs [8*tid, 8*tid+8): own window (pos j) + prev (pos j+8)
        {
            const int base8 = 8 * tid;
            s_xl[PADI(base8 + 0)] = gp[4].x * hq[8];   // own j=0 has hq[0]=0
            s_xl[PADI(base8 + 1)] = g[0].y * hq[1] + gp[4].y * hq[9];
            s_xl[PADI(base8 + 2)] = g[1].x * hq[2] + gp[5].x * hq[10];
            s_xl[PADI(base8 + 3)] = g[1].y * hq[3] + gp[5].y * hq[11];
            s_xl[PADI(base8 + 4)] = g[2].x * hq[4] + gp[6].x * hq[12];
            s_xl[PADI(base8 + 5)] = g[2].y * hq[5] + gp[6].y * hq[13];
            s_xl[PADI(base8 + 6)] = g[3].x * hq[6] + gp[7].x * hq[14];
            s_xl[PADI(base8 + 7)] = g[3].y * hq[7] + gp[7].y * hq[15];
        }
        __syncthreads();
    }

    // -------- global path: forward FFT, stage 0 reads packed padded s_time ---------
    float2 xr0, xr1, xr2, xr3;   // x kept for the residual add
    {
        float2 a = make_float2(s_time[PADI(2 * tid)], s_time[PADI(2 * tid + 1)]);
        float2 bb = make_float2(s_time[PADI(2 * (tid + 256))], s_time[PADI(2 * (tid + 256) + 1)]);
        float2 cc = make_float2(s_time[PADI(2 * (tid + 512))], s_time[PADI(2 * (tid + 512) + 1)]);
        float2 dd = make_float2(s_time[PADI(2 * (tid + 768))], s_time[PADI(2 * (tid + 768) + 1)]);
        xr0 = a; xr1 = bb; xr2 = cc; xr3 = dd;
        float2 w1 = __ldg(&g_tw[2 * tid]);
        float2 w2 = cmul(w1, w1);
        float2 w3 = cmul(w1, w2);
        float2 apc = cadd(a, cc);
        float2 amc = csub(a, cc);
        float2 bpd = cadd(bb, dd);
        float2 bmd = csub(bb, dd);
        int o = 4 * tid;
        float2 t1 = make_float2(amc.x + bmd.y, amc.y - bmd.x);
        float2 t3 = make_float2(amc.x - bmd.y, amc.y + bmd.x);
        bufB[o] = cadd(apc, bpd);
        bufB[o + 1] = cmul(t1, w1);
        bufB[o + 2] = cmul(csub(apc, bpd), w2);
        bufB[o + 3] = cmul(t3, w3);
    }
    __syncthreads();
    // stages 1..4: B->A->B->A->B
    {
        float2* src = bufB;
        float2* dst = bufA;
#pragma unroll
        for (int t = 1; t < 5; t++) {
            fstage<false>(src, dst, t, tid);
            __syncthreads();
            float2* tmp = src; src = dst; dst = tmp;
        }
    }
    // Z in bufB. merged: unpack -> filter/modrelu -> repack G into bufA
    {
        const float* mgb = g_mg + (b * HH + h) * GBB;
        const float* bgb = base_g + h * GBB;
        const float* bib = bias_g + h * GBB;
        float2* Z = bufB;
        float2* G = bufA;
        for (int k = tid; k <= 512; k += 256) {
            float2 Zk = Z[k & 1023];
            float2 Zm = Z[(1024 - k) & 1023];
            float2 tk = __ldg(&g_tw[k]);   // k <= 512
            float2 E = make_float2(0.5f * (Zk.x + Zm.x), 0.5f * (Zk.y - Zm.y));
            float2 O = make_float2(0.5f * (Zk.y + Zm.y), -0.5f * (Zk.x - Zm.x));
            float2 Xk = cadd(E, cmul(tk, O));
            Xk = filt_modrelu(Xk, invs * (bgb[k] + mgb[k]), bib[k]);
            float2 Xm;
            if (k < 512) {
                int kk = 1024 - k;
                float2 tkk = make_float2(-tk.x, tk.y);   // tws[kk] = -conj(tk)
                Xm = cadd(make_float2(E.x, -E.y), cmul(tkk, make_float2(O.x, -O.y)));
                Xm = filt_modrelu(Xm, invs * (bgb[kk] + mgb[kk]), bib[kk]);
            } else {
                Xm = Xk;
            }
            {
                float2 S = make_float2(Xk.x + Xm.x, Xk.y - Xm.y);
                float2 Dd = make_float2(Xk.x - Xm.x, Xk.y + Xm.y);
                float2 wc = make_float2(tk.x, -tk.y);   // conj(tws[k])
                float2 t = cmul(wc, Dd);
                G[k] = make_float2(S.x - t.y, S.y + t.x);
            }
            if (k > 0 && k < 512) {
                int jj = 1024 - k;
                float2 S = make_float2(Xm.x + Xk.x, Xm.y - Xk.y);
                float2 Dd = make_float2(Xm.x - Xk.x, Xm.y + Xk.y);
                float2 wc = make_float2(-tk.x, -tk.y);  // conj(tws[jj]) = -tk
                float2 t = cmul(wc, Dd);
                G[jj] = make_float2(S.x - t.y, S.y + t.x);
            }
        }
    }
    __syncthreads();

    // inverse FFT: stages 0..3 (A->B->A->B->A), final stage fused with y-store
    {
        float fw0 = fusion_w[0] * invs;   // hoisted: hide LDG under the stages
        float fw1 = fusion_w[1];
        float2* src = bufA;
        float2* dst = bufB;
#pragma unroll
        for (int t = 0; t < 4; t++) {
            fstage<true>(src, dst, t, tid);
            __syncthreads();
            float2* tmp = src; src = dst; dst = tmp;
        }
        // src == bufA. final stage: s=256, ps=0 -> unit twiddles; y = x + fused
        float2* orow2 = (float2*)row;
        float2 a = src[tid];
        float2 bb = src[tid + 256];
        float2 cc = src[tid + 512];
        float2 dd = src[tid + 768];
        float2 apc = cadd(a, cc);
        float2 amc = csub(a, cc);
        float2 bpd = cadd(bb, dd);
        float2 bmd = csub(bb, dd);
        float2 v0 = cadd(apc, bpd);                              // m = tid
        float2 v1 = make_float2(amc.x - bmd.y, amc.y + bmd.x);   // m = tid+256
        float2 v2 = csub(apc, bpd);                              // m = tid+512
        float2 v3 = make_float2(amc.x + bmd.y, amc.y - bmd.x);   // m = tid+768
        int m0 = tid, m1 = tid + 256, m2 = tid + 512, m3 = tid + 768;
        orow2[m0] = make_float2(xr0.x + fw0 * v0.x + fw1 * s_xl[PADI(2 * m0)],
                                xr0.y + fw0 * v0.y + fw1 * s_xl[PADI(2 * m0 + 1)]);
        orow2[m1] = make_float2(xr1.x + fw0 * v1.x + fw1 * s_xl[PADI(2 * m1)],
                                xr1.y + fw0 * v1.y + fw1 * s_xl[PADI(2 * m1 + 1)]);
        orow2[m2] = make_float2(xr2.x + fw0 * v2.x + fw1 * s_xl[PADI(2 * m2)],
                                xr2.y + fw0 * v2.y + fw1 * s_xl[PADI(2 * m2 + 1)]);
        orow2[m3] = make_float2(xr3.x + fw0 * v3.x + fw1 * s_xl[PADI(2 * m3)],
                                xr3.y + fw0 * v3.y + fw1 * s_xl[PADI(2 * m3 + 1)]);
    }
}

// ---------------- fused transpose-out + layernorm (y already includes residual) ----
__global__ __launch_bounds__(256) void ln_fused_kernel(const float* __restrict__ gamma,
                                                       const float* __restrict__ beta,
                                                       float* __restrict__ out) {
    __shared__ float tile[DD * 9];
    int n0 = blockIdx.x * 8;
    int b = blockIdx.y;
    int tid = threadIdx.x;

    const float* gx = g_xT + (size_t)b * DD * NN + n0;
    for (int idx = tid; idx < DD * 2; idx += 256) {
        int d = idx >> 1;
        int q = idx & 1;
        float4 v = ((const float4*)(gx + (size_t)d * NN))[q];
        float* tr = tile + d * 9 + 4 * q;
        tr[0] = v.x;
        tr[1] = v.y;
        tr[2] = v.z;
        tr[3] = v.w;
    }
    __syncthreads();

    int w = tid >> 5;
    int lane = tid & 31;
    int n = n0 + w;
    float* orow = out + ((size_t)b * NN + n) * DD;

    float y[24];
    float sum = 0.f;
#pragma unroll
    for (int i = 0; i < 24; i++) {
        int d = i * 32 + lane;
        float v = tile[d * 9 + w];
        y[i] = v;
        sum += v;
    }
#pragma unroll
    for (int o = 16; o > 0; o >>= 1) sum += __shfl_xor_sync(0xffffffffu, sum, o);
    float mu = sum * (1.0f / (float)DD);
    float vs = 0.f;
#pragma unroll
    for (int i = 0; i < 24; i++) {
        float d0 = y[i] - mu;
        y[i] = d0;
        vs += d0 * d0;
    }
#pragma unroll
    for (int o = 16; o > 0; o >>= 1) vs += __shfl_xor_sync(0xffffffffu, vs, o);
    float rstd = rsqrtf(vs * (1.0f / (float)DD) + 1e-5f);
#pragma unroll
    for (int i = 0; i < 24; i++) {
        int d = i * 32 + lane;
        orow[d] = y[i] * rstd * gamma[d] + beta[d];
    }
}

// ---------------- launch ----------------
extern "C" void kernel_launch(void* const* d_in, const int* in_sizes, int n_in,
                              void* d_out, int out_size) {
    const float* x = (const float*)d_in[0];
    const float* bf_g = (const float*)d_in[1];
    const float* bf_l = (const float*)d_in[2];
    const float* mb_g = (const float*)d_in[3];
    const float* mb_l = (const float*)d_in[4];
    const float* w1g = (const float*)d_in[5];
    const float* b1g = (const float*)d_in[6];
    const float* w2g = (const float*)d_in[7];
    const float* b2g = (const float*)d_in[8];
    const float* w1l = (const float*)d_in[9];
    const float* b1l = (const float*)d_in[10];
    const float* w2l = (const float*)d_in[11];
    const float* b2l = (const float*)d_in[12];
    const float* fw = (const float*)d_in[13];
    const float* gamma = (const float*)d_in[14];
    const float* beta = (const float*)d_in[15];
    float* out = (float*)d_out;

    tr_in_kernel<<<dim3(24, 64, 8), dim3(32, 8)>>>(x);                // 1 (+twiddles)
    mlp1_part_kernel<<<dim3(72, 8, 2), 128>>>(w1g, w1l);              // 2
    mlp1_fin_kernel<<<dim3(3, 8, 2), 128>>>(b1g, b1l);                // 3
    mlp2_part_kernel<<<dim3(50, KS2), 128>>>(w2g, w2l);               // 4
    mlp2_fin_kernel<<<dim3(50, 8), 128>>>(b2g, b2l);                  // 5
    spectral_kernel<<<BD * DD, 256>>>(bf_g, bf_l, mb_g, mb_l, fw);    // 6
    ln_fused_kernel<<<dim3(256, 8), 256>>>(gamma, beta, out);         // 7
}

// round 17
// speedup vs baseline: 1.0300x; 1.0300x over previous
#include <cuda_runtime.h>
#include <math.h>

#define BD 8
#define NN 2048
#define DD 768
#define HH 12
#define GBB 1025
#define LBB 9
#define NWW 255
#define HOPP 8
#define NCG (HH * GBB)  // 12300
#define NCL (HH * LBB)  // 108
#define NCG2 (NCG / 2)  // 6150 float2 columns
#define NCL2 (NCL / 2)  // 54
#define KS2 24          // mlp2 split-K chunks
#define PADI(n) ((n) + ((n) >> 4))

// ---------------- scratch ----------------
__device__ float g_xT[BD * DD * NN];        // (B, D, N): x^T, then y = x + fused
__device__ float g_ctxp[BD * 64 * DD];
__device__ float2 g_p1[2 * 24 * BD * (DD / 2)];
__device__ float g_hg[BD * DD];
__device__ float g_hl[BD * DD];
__device__ float2 g_pg[KS2 * BD * NCG2];
__device__ float2 g_pl[KS2 * BD * NCL2];
__device__ float g_mg[BD * NCG];
__device__ float g_ml[BD * NCL];
__device__ float2 g_tw[1025];               // exp(-i*pi*k/1024)

__device__ __forceinline__ float2 cmul(float2 a, float2 b) {
    return make_float2(a.x * b.x - a.y * b.y, a.x * b.y + a.y * b.x);
}
__device__ __forceinline__ float2 cadd(float2 a, float2 b) {
    return make_float2(a.x + b.x, a.y + b.y);
}
__device__ __forceinline__ float2 csub(float2 a, float2 b) {
    return make_float2(a.x - b.x, a.y - b.y);
}

// modrelu rescale: max(a+bias,0)/max(a,1e-6) with a=sqrt(m)
__device__ __forceinline__ float mr_scale(float m, float bias) {
    if (m >= 1e-12f) return fmaxf(fmaf(bias, rsqrtf(m), 1.0f), 0.0f);
    return fmaxf(sqrtf(m) + bias, 0.0f) * 1e6f;
}

__device__ __forceinline__ float2 filt_modrelu(float2 v, float pg, float bias) {
    v.x *= pg;
    v.y *= pg;
    float sc = mr_scale(v.x * v.x + v.y * v.y, bias);
    v.x *= sc;
    v.y *= sc;
    return v;
}

// ---------------- transpose in + ctx partials + twiddle init ----------------
__global__ __launch_bounds__(256) void tr_in_kernel(const float* __restrict__ x) {
    __shared__ float tile[32][33];
    __shared__ float red[8][32];
    int b = blockIdx.z;
    int d0 = blockIdx.x * 32;
    int n0 = blockIdx.y * 32;
    int tx = threadIdx.x, ty = threadIdx.y;
    int tid = ty * 32 + tx;

    if (blockIdx.y == 0 && blockIdx.z == 0) {
        int k = blockIdx.x * 256 + tid;
        if (k <= 1024) {
            float ang = -(float)M_PI * (float)k * (1.0f / 1024.0f);
            float sv, cv;
            sincosf(ang, &sv, &cv);
            g_tw[k] = make_float2(cv, sv);
        }
    }

    const float* xp = x + ((size_t)(b * NN + n0 + ty)) * DD + d0 + tx;
    float p = 0.f;
#pragma unroll
    for (int i = 0; i < 4; i++) {
        float v = xp[(size_t)i * 8 * DD];
        tile[ty + 8 * i][tx] = v;
        p += v;
    }
    red[ty][tx] = p;
    __syncthreads();
    if (ty == 0) {
        float s = 0.f;
#pragma unroll
        for (int j = 0; j < 8; j++) s += red[j][tx];
        g_ctxp[(size_t)(b * 64 + blockIdx.y) * DD + d0 + tx] = s;
    }
    float* op = g_xT + ((size_t)(b * DD + d0 + ty)) * NN + n0 + tx;
#pragma unroll
    for (int i = 0; i < 4; i++) op[(size_t)i * 8 * NN] = tile[tx][ty + 8 * i];
}

// ---------------- mlp layer 1 (split-K partials, float2 cols, ctx reduce folded) --
__global__ __launch_bounds__(128) void mlp1_part_kernel(const float* __restrict__ w1g,
                                                        const float* __restrict__ w1l) {
    int cb = blockIdx.x % 3;
    int ks = blockIdx.x / 3;   // 0..23
    int b = blockIdx.y;
    int z = blockIdx.z;
    const float2* w = (const float2*)(z ? w1l : w1g);
    __shared__ float csp[128];
    __shared__ float cs[32];
    int k0 = ks * 32;
    {
        int kk = threadIdx.x & 31;
        int sl = threadIdx.x >> 5;
        const float* pp = g_ctxp + (size_t)b * 64 * DD + k0 + kk + (size_t)sl * 16 * DD;
        float s = 0.f;
#pragma unroll
        for (int j = 0; j < 16; j++) s += pp[(size_t)j * DD];
        csp[threadIdx.x] = s;
    }
    __syncthreads();
    if (threadIdx.x < 32) {
        float s = csp[threadIdx.x] + csp[threadIdx.x + 32] + csp[threadIdx.x + 64] +
                  csp[threadIdx.x + 96];
        cs[threadIdx.x] = s * (1.0f / (float)NN);
    }
    __syncthreads();
    int c2 = cb * 128 + threadIdx.x;
    const float2* wp = w + (size_t)k0 * (DD / 2) + c2;
    float2 acc = make_float2(0.f, 0.f);
#pragma unroll
    for (int kk = 0; kk < 32; kk++) {
        float2 wv = wp[(size_t)kk * (DD / 2)];
        float cv = cs[kk];
        acc.x += cv * wv.x;
        acc.y += cv * wv.y;
    }
    g_p1[((z * 24 + ks) * BD + b) * (DD / 2) + c2] = acc;
}

// ---------------- mlp layer 1 finish: GELU (float2) ----------------
__global__ __launch_bounds__(128) void mlp1_fin_kernel(const float* __restrict__ b1g,
                                                       const float* __restrict__ b1l) {
    int c2 = blockIdx.x * 128 + threadIdx.x;
    int b = blockIdx.y;
    int z = blockIdx.z;
    const float2* bias = (const float2*)(z ? b1l : b1g);
    float2* out = (float2*)(z ? g_hl : g_hg);
    float2 s = bias[c2];
#pragma unroll
    for (int ks = 0; ks < 24; ks++) {
        float2 v = g_p1[((z * 24 + ks) * BD + b) * (DD / 2) + c2];
        s.x += v.x;
        s.y += v.y;
    }
    out[b * (DD / 2) + c2] =
        make_float2(0.5f * s.x * (1.0f + erff(s.x * 0.70710678118654752f)),
                    0.5f * s.y * (1.0f + erff(s.y * 0.70710678118654752f)));
}

// ---------------- mlp layer 2 (deep split-K, float2 columns) ----------------
__global__ __launch_bounds__(128) void mlp2_part_kernel(const float* __restrict__ w2g,
                                                        const float* __restrict__ w2l) {
    bool isl = (blockIdx.x == 49);
    int by = blockIdx.y;      // k-chunk 0..23
    int k0 = by * 32;
    __shared__ float hs[BD * 32];
    const float* h = isl ? g_hl : g_hg;
    if (threadIdx.x < BD * 32 / 2) {
        int i = threadIdx.x * 2;
        int b = i >> 5, kk = i & 31;
        hs[i] = h[b * DD + k0 + kk];
        hs[i + 1] = h[b * DD + k0 + kk + 1];
    }
    __syncthreads();
    int ncol2 = isl ? NCL2 : NCG2;
    int c2 = isl ? threadIdx.x : blockIdx.x * 128 + threadIdx.x;
    if (c2 >= ncol2) return;
    const float2* w = (const float2*)(isl ? w2l : w2g);
    float2* pp = isl ? g_pl : g_pg;
    float2 acc[BD];
#pragma unroll
    for (int b = 0; b < BD; b++) acc[b] = make_float2(0.f, 0.f);
    const float2* wp = w + (size_t)k0 * ncol2 + c2;
#pragma unroll
    for (int kk = 0; kk < 32; kk++) {
        float2 wv = wp[(size_t)kk * ncol2];
#pragma unroll
        for (int b = 0; b < BD; b++) {
            float hv = hs[b * 32 + kk];
            acc[b].x += hv * wv.x;
            acc[b].y += hv * wv.y;
        }
    }
#pragma unroll
    for (int b = 0; b < BD; b++) pp[(size_t)(by * BD + b) * ncol2 + c2] = acc[b];
}

__global__ __launch_bounds__(128) void mlp2_fin_kernel(const float* __restrict__ b2g,
                                                       const float* __restrict__ b2l) {
    bool isl = (blockIdx.x == 49);
    int ncol2 = isl ? NCL2 : NCG2;
    int c2 = isl ? threadIdx.x : blockIdx.x * 128 + threadIdx.x;
    if (c2 >= ncol2) return;
    int b = blockIdx.y;
    const float2* bias = (const float2*)(isl ? b2l : b2g);
    const float2* pp = isl ? g_pl : g_pg;
    float2* out = (float2*)(isl ? g_ml : g_mg);
    float2 s = bias[c2];
#pragma unroll
    for (int ks = 0; ks < KS2; ks++) {
        float2 v = pp[(size_t)(ks * BD + b) * ncol2 + c2];
        s.x += v.x;
        s.y += v.y;
    }
    out[(size_t)b * ncol2 + c2] = make_float2(tanhf(s.x), tanhf(s.y));
}

// ---------------- generic radix-4 Stockham stage (twiddle via __ldg, w2=w1^2) -----
template <bool INV>
__device__ __forceinline__ void fstage(const float2* __restrict__ src,
                                       float2* __restrict__ dst, int t, int tid) {
    const int s = 1 << (2 * t);
    int q = tid & (s - 1);
    int ps = tid - q;
    float2 a = src[tid];
    float2 b = src[tid + 256];
    float2 c = src[tid + 512];
    float2 d = src[tid + 768];
    float2 w1 = __ldg(&g_tw[2 * ps]);
    if (INV) w1.y = -w1.y;
    float2 w2 = cmul(w1, w1);
    float2 w3 = cmul(w1, w2);
    float2 apc = cadd(a, c);
    float2 amc = csub(a, c);
    float2 bpd = cadd(b, d);
    float2 bmd = csub(b, d);
    int o = 4 * tid - 3 * q;
    dst[o] = cadd(apc, bpd);
    float2 t1, t3;
    if (!INV) {
        t1 = make_float2(amc.x + bmd.y, amc.y - bmd.x);
        t3 = make_float2(amc.x - bmd.y, amc.y + bmd.x);
    } else {
        t1 = make_float2(amc.x - bmd.y, amc.y + bmd.x);
        t3 = make_float2(amc.x + bmd.y, amc.y - bmd.x);
    }
    dst[o + s] = cmul(t1, w1);
    dst[o + 2 * s] = cmul(csub(apc, bpd), w2);
    dst[o + 3 * s] = cmul(t3, w3);
}

__global__ __launch_bounds__(256) void spectral_kernel(
    const float* __restrict__ base_g, const float* __restrict__ base_l,
    const float* __restrict__ bias_g, const float* __restrict__ bias_l,
    const float* __restrict__ fusion_w) {
    __shared__ float2 uA[1088];        // union: padded s_time (2176 floats) / bufA
    __shared__ float2 bufB[1024];
    __shared__ float s_xl[2176];       // padded overlap-add output (write-once)
    __shared__ float2 glb[9];          // {0.25*(base+ml), bias} per local freq
    __shared__ float2 stg[8][8];       // warp-boundary staging for OA shuffle
    float2* bufA = uA;
    float* s_time = (float*)uA;

    const int tid = threadIdx.x;
    const int blk = blockIdx.x;
    const int b = blk / DD;
    const int c = blk - b * DD;
    const int h = c >> 6;
    const float invs = 0.022097086912079608f;  // 1/sqrt(2048)
    const float r2 = 0.70710678118654752f;

    if (tid < 9)
        glb[tid] = make_float2(0.25f * (base_l[h * LBB + tid] + g_ml[(b * HH + h) * LBB + tid]),
                               bias_l[h * LBB + tid]);

    float* row = g_xT + (size_t)blk * NN;
    {
        const float4* src4 = (const float4*)row;
        for (int i = tid; i < 512; i += 256) {
            float4 v = src4[i];
            int p = PADI(4 * i);
            s_time[p] = v.x;
            s_time[p + 1] = v.y;
            s_time[p + 2] = v.z;
            s_time[p + 3] = v.w;
        }
    }
    __syncthreads();

    // -------- local STFT: single pass; shuffle-based write-once overlap-add ------
    {
        const float hq[16] = {0.f, 0.25f * 0.03806023374435663f, 0.25f * 0.14644660940672624f,
                              0.25f * 0.30865828381745508f, 0.25f * 0.5f, 0.25f * 0.69134171618254492f,
                              0.25f * 0.85355339059327376f, 0.25f * 0.96193976625564337f, 0.25f * 1.f,
                              0.25f * 0.96193976625564337f, 0.25f * 0.85355339059327376f,
                              0.25f * 0.69134171618254492f, 0.25f * 0.5f, 0.25f * 0.30865828381745508f,
                              0.25f * 0.14644660940672624f, 0.25f * 0.03806023374435663f};
        const float hw[16] = {0.f, 0.03806023374435663f, 0.14644660940672624f, 0.30865828381745508f,
                              0.5f, 0.69134171618254492f, 0.85355339059327376f, 0.96193976625564337f,
                              1.f, 0.96193976625564337f, 0.85355339059327376f, 0.69134171618254492f,
                              0.5f, 0.30865828381745508f, 0.14644660940672624f, 0.03806023374435663f};
        const float cw[9] = {1.f, 0.92387953251128674f, r2, 0.38268343236508977f, 0.f,
                             -0.38268343236508977f, -r2, -0.92387953251128674f, -1.f};
        const float sw[9] = {0.f, 0.38268343236508977f, r2, 0.92387953251128674f, 1.f,
                             0.92387953251128674f, r2, 0.38268343236508977f, 0.f};

        float2 g[8];
#pragma unroll
        for (int m = 0; m < 8; m++) g[m] = make_float2(0.f, 0.f);
        const int nw = tid;
        const int base = nw * HOPP;
        if (nw < NWW) {
            float tw[16];
            tw[0] = 0.f;
#pragma unroll
            for (int j = 1; j < 16; j++) tw[j] = s_time[PADI(base + j)] * hw[j];

            float2 z[8];
#pragma unroll
            for (int m = 0; m < 8; m++) z[m] = make_float2(tw[2 * m], tw[2 * m + 1]);

            // forward FFT8 (DIF), output bit-reversed
            float2 Z[8];
            {
                float2 a0 = cadd(z[0], z[4]), d0 = csub(z[0], z[4]);
                float2 a1 = cadd(z[1], z[5]), d1 = csub(z[1], z[5]);
                float2 a2 = cadd(z[2], z[6]), d2 = csub(z[2], z[6]);
                float2 a3 = cadd(z[3], z[7]), d3 = csub(z[3], z[7]);
                float2 a4 = d0;
                float2 a5 = make_float2(r2 * (d1.x + d1.y), r2 * (d1.y - d1.x));
                float2 a6 = make_float2(d2.y, -d2.x);
                float2 a7 = make_float2(r2 * (d3.y - d3.x), -r2 * (d3.x + d3.y));

                float2 b0 = cadd(a0, a2), b2 = csub(a0, a2);
                float2 b1 = cadd(a1, a3), t13 = csub(a1, a3);
                float2 b3 = make_float2(t13.y, -t13.x);
                float2 b4 = cadd(a4, a6), b6 = csub(a4, a6);
                float2 b5 = cadd(a5, a7), t57 = csub(a5, a7);
                float2 b7 = make_float2(t57.y, -t57.x);

                Z[0] = cadd(b0, b1);
                Z[4] = csub(b0, b1);
                Z[2] = cadd(b2, b3);
                Z[6] = csub(b2, b3);
                Z[1] = cadd(b4, b5);
                Z[5] = csub(b4, b5);
                Z[3] = cadd(b6, b7);
                Z[7] = csub(b6, b7);
            }

            // unpack to rfft16 + filter + modrelu
            float2 X[9];
#pragma unroll
            for (int k = 0; k <= 4; k++) {
                float2 Zk = Z[k];
                float2 Zm = Z[(8 - k) & 7];
                float2 E = make_float2(0.5f * (Zk.x + Zm.x), 0.5f * (Zk.y - Zm.y));
                float2 O = make_float2(0.5f * (Zk.y + Zm.y), -0.5f * (Zk.x - Zm.x));
                float2 w = make_float2(cw[k], -sw[k]);
                float2 Xk = cadd(E, cmul(w, O));
                float2 gb = glb[k];
                X[k] = filt_modrelu(Xk, gb.x, gb.y);
                if (k > 0 && k < 4) {
                    int kk = 8 - k;
                    float2 wm = make_float2(cw[kk], -sw[kk]);
                    float2 Xm = cadd(make_float2(E.x, -E.y), cmul(wm, make_float2(O.x, -O.y)));
                    float2 gb2 = glb[kk];
                    X[kk] = filt_modrelu(Xm, gb2.x, gb2.y);
                } else if (k == 0) {
                    float2 Xm = make_float2(E.x - O.x, O.y - E.y);
                    float2 gb2 = glb[8];
                    X[8] = filt_modrelu(Xm, gb2.x, gb2.y);
                }
            }

            // repack: G[m] = S + i*conj(w16^m)*D
            float2 G[8];
#pragma unroll
            for (int m = 0; m < 8; m++) {
                float2 Xa = X[m];
                float2 Xb = X[8 - m];
                float2 S = make_float2(Xa.x + Xb.x, Xa.y - Xb.y);
                float2 D = make_float2(Xa.x - Xb.x, Xa.y + Xb.y);
                float2 wc = make_float2(cw[m], sw[m]);
                float2 t = cmul(wc, D);
                G[m] = make_float2(S.x - t.y, S.y + t.x);
            }

            // inverse FFT8 (conjugate twiddles), output bit-reversed
            {
                float2 a0 = cadd(G[0], G[4]), d0 = csub(G[0], G[4]);
                float2 a1 = cadd(G[1], G[5]), d1 = csub(G[1], G[5]);
                float2 a2 = cadd(G[2], G[6]), d2 = csub(G[2], G[6]);
                float2 a3 = cadd(G[3], G[7]), d3 = csub(G[3], G[7]);
                float2 a4 = d0;
                float2 a5 = make_float2(r2 * (d1.x - d1.y), r2 * (d1.x + d1.y));
                float2 a6 = make_float2(-d2.y, d2.x);
                float2 a7 = make_float2(-r2 * (d3.x + d3.y), r2 * (d3.x - d3.y));

                float2 b0 = cadd(a0, a2), b2 = csub(a0, a2);
                float2 b1 = cadd(a1, a3), t13 = csub(a1, a3);
                float2 b3 = make_float2(-t13.y, t13.x);
                float2 b4 = cadd(a4, a6), b6 = csub(a4, a6);
                float2 b5 = cadd(a5, a7), t57 = csub(a5, a7);
                float2 b7 = make_float2(-t57.y, t57.x);

                g[0] = cadd(b0, b1);
                g[4] = csub(b0, b1);
                g[2] = cadd(b2, b3);
                g[6] = csub(b2, b3);
                g[1] = cadd(b4, b5);
                g[5] = csub(b4, b5);
                g[3] = cadd(b6, b7);
                g[7] = csub(b6, b7);
            }
        }

        // fetch previous window's iFFT via shuffle (warp boundary via SMEM stage)
        float2 gp[8];
#pragma unroll
        for (int m = 0; m < 8; m++) {
            gp[m].x = __shfl_up_sync(0xffffffffu, g[m].x, 1);
            gp[m].y = __shfl_up_sync(0xffffffffu, g[m].y, 1);
        }
        int lane = tid & 31;
        if (lane == 31) {
#pragma unroll
            for (int m = 0; m < 8; m++) stg[tid >> 5][m] = g[m];
        }
        __syncthreads();
        if (lane == 0) {
            if (tid == 0) {
#pragma unroll
                for (int m = 0; m < 8; m++) gp[m] = make_float2(0.f, 0.f);
            } else {
#pragma unroll
                for (int m = 0; m < 8; m++) gp[m] = stg[(tid >> 5) - 1][m];
            }
        }
        // thread tid owns outputs [8*tid, 8*tid+8); s_xl consumed only after the
        // FFT stage barriers below, so no extra barrier needed here.
        {
            const int base8 = 8 * tid;
            s_xl[PADI(base8 + 0)] = gp[4].x * hq[8];   // own j=0 has hq[0]=0
            s_xl[PADI(base8 + 1)] = g[0].y * hq[1] + gp[4].y * hq[9];
            s_xl[PADI(base8 + 2)] = g[1].x * hq[2] + gp[5].x * hq[10];
            s_xl[PADI(base8 + 3)] = g[1].y * hq[3] + gp[5].y * hq[11];
            s_xl[PADI(base8 + 4)] = g[2].x * hq[4] + gp[6].x * hq[12];
            s_xl[PADI(base8 + 5)] = g[2].y * hq[5] + gp[6].y * hq[13];
            s_xl[PADI(base8 + 6)] = g[3].x * hq[6] + gp[7].x * hq[14];
            s_xl[PADI(base8 + 7)] = g[3].y * hq[7] + gp[7].y * hq[15];
        }
    }

    // -------- global path: forward FFT, stage 0 reads packed padded s_time ---------
    float2 xr0, xr1, xr2, xr3;   // x kept for the residual add
    {
        float2 a = make_float2(s_time[PADI(2 * tid)], s_time[PADI(2 * tid + 1)]);
        float2 bb = make_float2(s_time[PADI(2 * (tid + 256))], s_time[PADI(2 * (tid + 256) + 1)]);
        float2 cc = make_float2(s_time[PADI(2 * (tid + 512))], s_time[PADI(2 * (tid + 512) + 1)]);
        float2 dd = make_float2(s_time[PADI(2 * (tid + 768))], s_time[PADI(2 * (tid + 768) + 1)]);
        xr0 = a; xr1 = bb; xr2 = cc; xr3 = dd;
        float2 w1 = __ldg(&g_tw[2 * tid]);
        float2 w2 = cmul(w1, w1);
        float2 w3 = cmul(w1, w2);
        float2 apc = cadd(a, cc);
        float2 amc = csub(a, cc);
        float2 bpd = cadd(bb, dd);
        float2 bmd = csub(bb, dd);
        int o = 4 * tid;
        float2 t1 = make_float2(amc.x + bmd.y, amc.y - bmd.x);
        float2 t3 = make_float2(amc.x - bmd.y, amc.y + bmd.x);
        bufB[o] = cadd(apc, bpd);
        bufB[o + 1] = cmul(t1, w1);
        bufB[o + 2] = cmul(csub(apc, bpd), w2);
        bufB[o + 3] = cmul(t3, w3);
    }
    __syncthreads();
    // stages 1..4: B->A->B->A->B
    {
        float2* src = bufB;
        float2* dst = bufA;
#pragma unroll
        for (int t = 1; t < 5; t++) {
            fstage<false>(src, dst, t, tid);
            __syncthreads();
            float2* tmp = src; src = dst; dst = tmp;
        }
    }
    // Z in bufB. merged: unpack -> filter/modrelu -> repack G into bufA
    {
        const float* mgb = g_mg + (b * HH + h) * GBB;
        const float* bgb = base_g + h * GBB;
        const float* bib = bias_g + h * GBB;
        float2* Z = bufB;
        float2* G = bufA;
        for (int k = tid; k <= 512; k += 256) {
            float2 Zk = Z[k & 1023];
            float2 Zm = Z[(1024 - k) & 1023];
            float2 tk = __ldg(&g_tw[k]);   // k <= 512
            float2 E = make_float2(0.5f * (Zk.x + Zm.x), 0.5f * (Zk.y - Zm.y));
            float2 O = make_float2(0.5f * (Zk.y + Zm.y), -0.5f * (Zk.x - Zm.x));
            float2 Xk = cadd(E, cmul(tk, O));
            Xk = filt_modrelu(Xk, invs * (bgb[k] + mgb[k]), bib[k]);
            float2 Xm;
            if (k < 512) {
                int kk = 1024 - k;
                float2 tkk = make_float2(-tk.x, tk.y);   // tws[kk] = -conj(tk)
                Xm = cadd(make_float2(E.x, -E.y), cmul(tkk, make_float2(O.x, -O.y)));
                Xm = filt_modrelu(Xm, invs * (bgb[kk] + mgb[kk]), bib[kk]);
            } else {
                Xm = Xk;
            }
            {
                float2 S = make_float2(Xk.x + Xm.x, Xk.y - Xm.y);
                float2 Dd = make_float2(Xk.x - Xm.x, Xk.y + Xm.y);
                float2 wc = make_float2(tk.x, -tk.y);   // conj(tws[k])
                float2 t = cmul(wc, Dd);
                G[k] = make_float2(S.x - t.y, S.y + t.x);
            }
            if (k > 0 && k < 512) {
                int jj = 1024 - k;
                float2 S = make_float2(Xm.x + Xk.x, Xm.y - Xk.y);
                float2 Dd = make_float2(Xm.x - Xk.x, Xm.y + Xk.y);
                float2 wc = make_float2(-tk.x, -tk.y);  // conj(tws[jj]) = -tk
                float2 t = cmul(wc, Dd);
                G[jj] = make_float2(S.x - t.y, S.y + t.x);
            }
        }
    }
    __syncthreads();

    // inverse FFT: stages 0..3 (A->B->A->B->A), final stage fused with y-store
    {
        float fw0 = fusion_w[0] * invs;   // hoisted: hide LDG under the stages
        float fw1 = fusion_w[1];
        float2* src = bufA;
        float2* dst = bufB;
#pragma unroll
        for (int t = 0; t < 4; t++) {
            fstage<true>(src, dst, t, tid);
            __syncthreads();
            float2* tmp = src; src = dst; dst = tmp;
        }
        // src == bufA. final stage: s=256, ps=0 -> unit twiddles; y = x + fused
        float2* orow2 = (float2*)row;
        float2 a = src[tid];
        float2 bb = src[tid + 256];
        float2 cc = src[tid + 512];
        float2 dd = src[tid + 768];
        float2 apc = cadd(a, cc);
        float2 amc = csub(a, cc);
        float2 bpd = cadd(bb, dd);
        float2 bmd = csub(bb, dd);
        float2 v0 = cadd(apc, bpd);                              // m = tid
        float2 v1 = make_float2(amc.x - bmd.y, amc.y + bmd.x);   // m = tid+256
        float2 v2 = csub(apc, bpd);                              // m = tid+512
        float2 v3 = make_float2(amc.x + bmd.y, amc.y - bmd.x);   // m = tid+768
        int m0 = tid, m1 = tid + 256, m2 = tid + 512, m3 = tid + 768;
        orow2[m0] = make_float2(xr0.x + fw0 * v0.x + fw1 * s_xl[PADI(2 * m0)],
                                xr0.y + fw0 * v0.y + fw1 * s_xl[PADI(2 * m0 + 1)]);
        orow2[m1] = make_float2(xr1.x + fw0 * v1.x + fw1 * s_xl[PADI(2 * m1)],
                                xr1.y + fw0 * v1.y + fw1 * s_xl[PADI(2 * m1 + 1)]);
        orow2[m2] = make_float2(xr2.x + fw0 * v2.x + fw1 * s_xl[PADI(2 * m2)],
                                xr2.y + fw0 * v2.y + fw1 * s_xl[PADI(2 * m2 + 1)]);
        orow2[m3] = make_float2(xr3.x + fw0 * v3.x + fw1 * s_xl[PADI(2 * m3)],
                                xr3.y + fw0 * v3.y + fw1 * s_xl[PADI(2 * m3 + 1)]);
    }
}

// ---------------- fused transpose-out + layernorm (y already includes residual) ----
__global__ __launch_bounds__(256) void ln_fused_kernel(const float* __restrict__ gamma,
                                                       const float* __restrict__ beta,
                                                       float* __restrict__ out) {
    __shared__ float tile[DD * 9];
    int n0 = blockIdx.x * 8;
    int b = blockIdx.y;
    int tid = threadIdx.x;

    const float* gx = g_xT + (size_t)b * DD * NN + n0;
    for (int idx = tid; idx < DD * 2; idx += 256) {
        int d = idx >> 1;
        int q = idx & 1;
        float4 v = ((const float4*)(gx + (size_t)d * NN))[q];
        float* tr = tile + d * 9 + 4 * q;
        tr[0] = v.x;
        tr[1] = v.y;
        tr[2] = v.z;
        tr[3] = v.w;
    }
    __syncthreads();

    int w = tid >> 5;
    int lane = tid & 31;
    int n = n0 + w;
    float* orow = out + ((size_t)b * NN + n) * DD;

    float y[24];
    float sum = 0.f;
#pragma unroll
    for (int i = 0; i < 24; i++) {
        int d = i * 32 + lane;
        float v = tile[d * 9 + w];
        y[i] = v;
        sum += v;
    }
#pragma unroll
    for (int o = 16; o > 0; o >>= 1) sum += __shfl_xor_sync(0xffffffffu, sum, o);
    float mu = sum * (1.0f / (float)DD);
    float vs = 0.f;
#pragma unroll
    for (int i = 0; i < 24; i++) {
        float d0 = y[i] - mu;
        y[i] = d0;
        vs += d0 * d0;
    }
#pragma unroll
    for (int o = 16; o > 0; o >>= 1) vs += __shfl_xor_sync(0xffffffffu, vs, o);
    float rstd = rsqrtf(vs * (1.0f / (float)DD) + 1e-5f);
#pragma unroll
    for (int i = 0; i < 24; i++) {
        int d = i * 32 + lane;
        orow[d] = y[i] * rstd * gamma[d] + beta[d];
    }
}

// ---------------- launch ----------------
extern "C" void kernel_launch(void* const* d_in, const int* in_sizes, int n_in,
                              void* d_out, int out_size) {
    const float* x = (const float*)d_in[0];
    const float* bf_g = (const float*)d_in[1];
    const float* bf_l = (const float*)d_in[2];
    const float* mb_g = (const float*)d_in[3];
    const float* mb_l = (const float*)d_in[4];
    const float* w1g = (const float*)d_in[5];
    const float* b1g = (const float*)d_in[6];
    const float* w2g = (const float*)d_in[7];
    const float* b2g = (const float*)d_in[8];
    const float* w1l = (const float*)d_in[9];
    const float* b1l = (const float*)d_in[10];
    const float* w2l = (const float*)d_in[11];
    const float* b2l = (const float*)d_in[12];
    const float* fw = (const float*)d_in[13];
    const float* gamma = (const float*)d_in[14];
    const float* beta = (const float*)d_in[15];
    float* out = (float*)d_out;

    tr_in_kernel<<<dim3(24, 64, 8), dim3(32, 8)>>>(x);                // 1 (+twiddles)
    mlp1_part_kernel<<<dim3(72, 8, 2), 128>>>(w1g, w1l);              // 2
    mlp1_fin_kernel<<<dim3(3, 8, 2), 128>>>(b1g, b1l);                // 3
    mlp2_part_kernel<<<dim3(50, KS2), 128>>>(w2g, w2l);               // 4
    mlp2_fin_kernel<<<dim3(50, 8), 128>>>(b2g, b2l);                  // 5
    spectral_kernel<<<BD * DD, 256>>>(bf_g, bf_l, mb_g, mb_l, fw);    // 6
    ln_fused_kernel<<<dim3(256, 8), 256>>>(gamma, beta, out);         // 7
}